// round 1
// baseline (speedup 1.0000x reference)
#include <cuda_runtime.h>

// TopKRouter: logits = x @ w_gate^T ; softmax ; top-2 ; renorm.
// x: [B*S=16384, D=2048] f32, w_gate: [E=64, D=2048] f32.
// Output layout (float32, concatenated reference outputs):
//   [0      , 32768)   topk_idx  as float  [B,S,2]
//   [32768  , 65536)   topk_probs          [B,S,2]
//   [65536  , 1114112) probs               [B,S,64]

#define D_DIM 2048
#define E_DIM 64
#define BS    16384
#define TM    64
#define TK    32
#define THREADS 256
#define EPS   1e-9f

__global__ __launch_bounds__(THREADS, 2)
void topk_router_kernel(const float* __restrict__ x,
                        const float* __restrict__ w,
                        float* __restrict__ out)
{
    __shared__ float xs[TK][TM + 4];   // x tile, transposed: xs[k][m]
    __shared__ float ws[TK][E_DIM + 4];// w tile, transposed: ws[k][e]
    __shared__ float ls[TM][E_DIM + 1];// logits staging for epilogue

    const int tid = threadIdx.x;
    const int tx  = tid & 15;          // expert group (16 x 4 = 64 experts)
    const int ty  = tid >> 4;          // token group  (16 x 4 = 64 tokens)
    const int m0  = blockIdx.x * TM;

    float acc[4][4] = {};

    for (int k0 = 0; k0 < D_DIM; k0 += TK) {
        // ---- stage tiles: 64 rows x 32 k as 512 float4s, 2 per thread ----
        #pragma unroll
        for (int i = 0; i < 2; i++) {
            int f   = tid + i * THREADS;
            int row = f >> 3;            // 0..63
            int c4  = (f & 7) << 2;      // 0,4,...,28
            float4 v = *(const float4*)&x[(size_t)(m0 + row) * D_DIM + k0 + c4];
            xs[c4 + 0][row] = v.x; xs[c4 + 1][row] = v.y;
            xs[c4 + 2][row] = v.z; xs[c4 + 3][row] = v.w;
            float4 u = *(const float4*)&w[(size_t)row * D_DIM + k0 + c4];
            ws[c4 + 0][row] = u.x; ws[c4 + 1][row] = u.y;
            ws[c4 + 2][row] = u.z; ws[c4 + 3][row] = u.w;
        }
        __syncthreads();

        // ---- 4x4 microtile FMAs over the k slice ----
        #pragma unroll
        for (int kk = 0; kk < TK; kk++) {
            float4 a = *(const float4*)&xs[kk][ty << 2];
            float4 b = *(const float4*)&ws[kk][tx << 2];
            float av[4] = {a.x, a.y, a.z, a.w};
            float bv[4] = {b.x, b.y, b.z, b.w};
            #pragma unroll
            for (int i = 0; i < 4; i++)
                #pragma unroll
                for (int j = 0; j < 4; j++)
                    acc[i][j] = fmaf(av[i], bv[j], acc[i][j]);
        }
        __syncthreads();
    }

    // ---- stash logits tile to smem ----
    #pragma unroll
    for (int i = 0; i < 4; i++)
        #pragma unroll
        for (int j = 0; j < 4; j++)
            ls[(ty << 2) + i][(tx << 2) + j] = acc[i][j];
    __syncthreads();

    // ---- fused softmax + top-2 epilogue: one token per thread (0..63) ----
    if (tid < TM) {
        const int token = m0 + tid;
        float* __restrict__ out_idx = out;
        float* __restrict__ out_tp  = out + 2 * BS;
        float* __restrict__ out_p   = out + 4 * BS;

        float mx = -1e30f;
        #pragma unroll
        for (int e = 0; e < E_DIM; e++)
            mx = fmaxf(mx, ls[tid][e]);

        float sum = 0.0f;
        #pragma unroll
        for (int e = 0; e < E_DIM; e++)
            sum += expf(ls[tid][e] - mx);
        float inv = 1.0f / sum;

        float p1 = -1.0f, p2 = -1.0f;
        int   i1 = 0,     i2 = 0;
        #pragma unroll
        for (int e = 0; e < E_DIM; e++) {
            float p = expf(ls[tid][e] - mx) * inv;
            out_p[(size_t)token * E_DIM + e] = p;
            if (p > p1)      { p2 = p1; i2 = i1; p1 = p; i1 = e; }
            else if (p > p2) { p2 = p;  i2 = e; }
        }

        float denom = p1 + p2 + EPS;
        out_idx[token * 2 + 0] = (float)i1;
        out_idx[token * 2 + 1] = (float)i2;
        out_tp [token * 2 + 0] = p1 / denom;
        out_tp [token * 2 + 1] = p2 / denom;
    }
}

extern "C" void kernel_launch(void* const* d_in, const int* in_sizes, int n_in,
                              void* d_out, int out_size)
{
    const float* x = (const float*)d_in[0];   // [4*4096, 2048]
    const float* w = (const float*)d_in[1];   // [64, 2048]
    float* out = (float*)d_out;

    dim3 grid(BS / TM);   // 256 CTAs
    topk_router_kernel<<<grid, THREADS>>>(x, w, out);
}

// round 3
// speedup vs baseline: 1.6673x; 1.6673x over previous
#include <cuda_runtime.h>
#include <cuda_bf16.h>
#include <cstdint>

// TopKRouter via mma.sync bf16 triple-split (residual ~2^-24 ≈ fp32).
// logits[16384,64] = x[16384,2048] @ w[64,2048]^T ; softmax ; top-2 ; renorm.
// out (f32): [0,32768) topk_idx ; [32768,65536) topk_probs ; [65536,..) probs.

#define D_DIM   2048
#define E_DIM   64
#define BSZ     16384
#define TM      128
#define KC      32
#define NCHUNK  (D_DIM / KC)
#define THREADS 256
#define EPS     1e-9f

// smem layout (per buffer): A splits then B splits
#define A_STRIDE 80                    // bytes per token row (32 bf16 = 64B + pad)
#define A_SPLIT  (TM * A_STRIDE)       // 10240
#define B_OFF    (3 * A_SPLIT)         // 30720
#define B_STRIDE 144                   // bytes per k row (64 bf16 = 128B + pad)
#define B_SPLIT  (KC * B_STRIDE)       // 4608
#define SBUF     (B_OFF + 3 * B_SPLIT) // 44544
#define SMEM_TOTAL (2 * SBUF)          // 89088
#define LS_STRIDE 72                   // floats per logits row (64 + pad)

__device__ __nv_bfloat16 g_wt[3u * D_DIM * E_DIM];  // [split][k][n]

__global__ void prep_w_kernel(const float* __restrict__ w) {
    int idx = blockIdx.x * blockDim.x + threadIdx.x;   // n*2048 + k
    if (idx >= E_DIM * D_DIM) return;
    int n = idx >> 11;
    int k = idx & (D_DIM - 1);
    float v = w[idx];
    __nv_bfloat16 bh = __float2bfloat16_rn(v);
    float r1 = v - __bfloat162float(bh);
    __nv_bfloat16 bm = __float2bfloat16_rn(r1);
    float r2 = r1 - __bfloat162float(bm);
    __nv_bfloat16 bl = __float2bfloat16_rn(r2);
    g_wt[0 * D_DIM * E_DIM + k * E_DIM + n] = bh;
    g_wt[1 * D_DIM * E_DIM + k * E_DIM + n] = bm;
    g_wt[2 * D_DIM * E_DIM + k * E_DIM + n] = bl;
}

__device__ __forceinline__ uint32_t smem_u32(const void* p) {
    uint32_t a;
    asm("{ .reg .u64 t; cvta.to.shared.u64 t, %1; cvt.u32.u64 %0, t; }" : "=r"(a) : "l"(p));
    return a;
}
__device__ __forceinline__ void ldsm4(uint32_t* r, uint32_t addr) {
    asm volatile("ldmatrix.sync.aligned.m8n8.x4.shared.b16 {%0,%1,%2,%3}, [%4];"
        : "=r"(r[0]), "=r"(r[1]), "=r"(r[2]), "=r"(r[3]) : "r"(addr));
}
__device__ __forceinline__ void ldsm4t(uint32_t* r, uint32_t addr) {
    asm volatile("ldmatrix.sync.aligned.m8n8.x4.trans.shared.b16 {%0,%1,%2,%3}, [%4];"
        : "=r"(r[0]), "=r"(r[1]), "=r"(r[2]), "=r"(r[3]) : "r"(addr));
}
__device__ __forceinline__ void mma16816(float* d, const uint32_t* a,
                                         uint32_t b0, uint32_t b1) {
    asm volatile(
        "mma.sync.aligned.m16n8k16.row.col.f32.bf16.bf16.f32 "
        "{%0,%1,%2,%3}, {%4,%5,%6,%7}, {%8,%9}, {%0,%1,%2,%3};"
        : "+f"(d[0]), "+f"(d[1]), "+f"(d[2]), "+f"(d[3])
        : "r"(a[0]), "r"(a[1]), "r"(a[2]), "r"(a[3]), "r"(b0), "r"(b1));
}

__device__ __forceinline__ uint32_t pack2(__nv_bfloat16 a, __nv_bfloat16 b) {
    __nv_bfloat162 t; t.x = a; t.y = b;
    return *(uint32_t*)&t;
}

__global__ __launch_bounds__(THREADS, 1)
void topk_router_mma(const float* __restrict__ x, float* __restrict__ out)
{
    extern __shared__ char smem[];
    const uint32_t sbase = smem_u32(smem);
    const int tid  = threadIdx.x;
    const int wid  = tid >> 5;
    const int lane = tid & 31;
    const int wm   = wid >> 1;     // 0..3  (32-row slice)
    const int wn   = wid & 1;      // 0..1  (32-col slice)
    const int m0   = blockIdx.x * TM;

    // per-lane ldmatrix base addresses (within buffer 0)
    uint32_t a_base[2][3], b_base[2][3];
    {
        const int arow = wm * 32 + (lane & 15);
        const int acol = (lane >> 4) * 16;              // bytes
        const int bk   = (lane & 7) + 8 * ((lane >> 3) & 1);
        const int bcol = (lane >> 4) * 16;              // bytes
        #pragma unroll
        for (int s = 0; s < 3; s++) {
            a_base[0][s] = sbase + s * A_SPLIT + arow * A_STRIDE + acol;
            a_base[1][s] = a_base[0][s] + 16 * A_STRIDE;
            b_base[0][s] = sbase + B_OFF + s * B_SPLIT + bk * B_STRIDE
                         + (wn * 32) * 2 + bcol;
            b_base[1][s] = b_base[0][s] + 32;           // +16 cols
        }
    }

    // LDG mapping: x -> row = tid>>1, k half = (tid&1)*16 ; w -> 3 uint4
    const int xrow = tid >> 1;
    const int xkb  = (tid & 1) * 16;
    const size_t xbase = (size_t)(m0 + xrow) * D_DIM + xkb;
    float4 xv[4];
    uint4  wv[3];

    #define LDG_CHUNK(c) do {                                                 \
        const int k0_ = (c) * KC;                                             \
        _Pragma("unroll")                                                     \
        for (int i = 0; i < 4; i++)                                           \
            xv[i] = *(const float4*)&x[xbase + k0_ + i * 4];                  \
        _Pragma("unroll")                                                     \
        for (int s = 0; s < 3; s++)                                           \
            wv[s] = *(const uint4*)&g_wt[(size_t)s * D_DIM * E_DIM            \
                     + (size_t)(k0_ + (tid >> 3)) * E_DIM + (tid & 7) * 8];   \
    } while (0)

    #define STS_CHUNK(bufoff) do {                                            \
        _Pragma("unroll")                                                     \
        for (int s = 0; s < 3; s++)                                           \
            *(uint4*)(smem + (bufoff) + B_OFF + s * B_SPLIT                   \
                      + (tid >> 3) * B_STRIDE + (tid & 7) * 16) = wv[s];      \
        _Pragma("unroll")                                                     \
        for (int i = 0; i < 4; i++) {                                         \
            float vv[4] = {xv[i].x, xv[i].y, xv[i].z, xv[i].w};               \
            __nv_bfloat16 hh[4], mm[4], ll[4];                                \
            _Pragma("unroll")                                                 \
            for (int e = 0; e < 4; e++) {                                     \
                hh[e] = __float2bfloat16_rn(vv[e]);                           \
                float r1 = vv[e] - __bfloat162float(hh[e]);                   \
                mm[e] = __float2bfloat16_rn(r1);                              \
                float r2 = r1 - __bfloat162float(mm[e]);                      \
                ll[e] = __float2bfloat16_rn(r2);                              \
            }                                                                 \
            char* pa = smem + (bufoff) + xrow * A_STRIDE + (xkb + i * 4) * 2; \
            *(uint2*)(pa + 0 * A_SPLIT) =                                     \
                make_uint2(pack2(hh[0], hh[1]), pack2(hh[2], hh[3]));         \
            *(uint2*)(pa + 1 * A_SPLIT) =                                     \
                make_uint2(pack2(mm[0], mm[1]), pack2(mm[2], mm[3]));         \
            *(uint2*)(pa + 2 * A_SPLIT) =                                     \
                make_uint2(pack2(ll[0], ll[1]), pack2(ll[2], ll[3]));         \
        }                                                                     \
    } while (0)

    float acc[8][4];
    #pragma unroll
    for (int t = 0; t < 8; t++)
        #pragma unroll
        for (int j = 0; j < 4; j++) acc[t][j] = 0.0f;

    LDG_CHUNK(0);
    STS_CHUNK(0);
    __syncthreads();

    #pragma unroll 1
    for (int c = 0; c < NCHUNK; c++) {
        const uint32_t bo = (c & 1) ? SBUF : 0u;
        if (c + 1 < NCHUNK) LDG_CHUNK(c + 1);

        // ---- compute chunk c from buffer bo ----
        #pragma unroll
        for (int ks = 0; ks < 2; ks++) {
            uint32_t a[2][3][4];
            #pragma unroll
            for (int mt = 0; mt < 2; mt++)
                #pragma unroll
                for (int s = 0; s < 3; s++)
                    ldsm4(a[mt][s], a_base[mt][s] + bo + ks * 32);
            #pragma unroll
            for (int ng = 0; ng < 2; ng++) {
                uint32_t b[3][4];
                #pragma unroll
                for (int s = 0; s < 3; s++)
                    ldsm4t(b[s], b_base[ng][s] + bo + ks * (16 * B_STRIDE));
                #pragma unroll
                for (int mt = 0; mt < 2; mt++)
                    #pragma unroll
                    for (int h = 0; h < 2; h++) {
                        float* d = acc[(mt * 2 + ng) * 2 + h];
                        mma16816(d, a[mt][0], b[0][2*h], b[0][2*h+1]); // h*h
                        mma16816(d, a[mt][0], b[1][2*h], b[1][2*h+1]); // h*m
                        mma16816(d, a[mt][1], b[0][2*h], b[0][2*h+1]); // m*h
                        mma16816(d, a[mt][0], b[2][2*h], b[2][2*h+1]); // h*l
                        mma16816(d, a[mt][2], b[0][2*h], b[0][2*h+1]); // l*h
                        mma16816(d, a[mt][1], b[1][2*h], b[1][2*h+1]); // m*m
                    }
            }
        }

        if (c + 1 < NCHUNK) STS_CHUNK((c & 1) ? 0u : SBUF);
        __syncthreads();
    }

    // ---- stash logits to smem (overlay buffer 0) ----
    float* ls = (float*)smem;
    #pragma unroll
    for (int mt = 0; mt < 2; mt++)
        #pragma unroll
        for (int ng = 0; ng < 2; ng++)
            #pragma unroll
            for (int h = 0; h < 2; h++) {
                const float* d = acc[(mt * 2 + ng) * 2 + h];
                int row = wm * 32 + mt * 16 + (lane >> 2);
                int col = wn * 32 + ng * 16 + h * 8 + 2 * (lane & 3);
                *(float2*)&ls[row * LS_STRIDE + col] = make_float2(d[0], d[1]);
                *(float2*)&ls[(row + 8) * LS_STRIDE + col] = make_float2(d[2], d[3]);
            }
    __syncthreads();

    // ---- softmax + top-2, one token per thread ----
    if (tid < TM) {
        const int token = m0 + tid;
        float* row = &ls[tid * LS_STRIDE];

        float mx = -1e30f;
        #pragma unroll
        for (int e = 0; e < E_DIM; e++) mx = fmaxf(mx, row[e]);

        float sum = 0.0f;
        #pragma unroll
        for (int e = 0; e < E_DIM; e++) {
            float ev = expf(row[e] - mx);
            row[e] = ev;
            sum += ev;
        }
        float inv = 1.0f / sum;

        float* __restrict__ out_p = out + 4 * BSZ + (size_t)token * E_DIM;
        float p1 = -1.0f, p2 = -1.0f;
        int   i1 = 0,     i2 = 0;
        #pragma unroll
        for (int e = 0; e < E_DIM; e += 4) {
            float4 pv = make_float4(row[e] * inv, row[e+1] * inv,
                                    row[e+2] * inv, row[e+3] * inv);
            *(float4*)&out_p[e] = pv;
            float pe[4] = {pv.x, pv.y, pv.z, pv.w};
            #pragma unroll
            for (int j = 0; j < 4; j++) {
                if (pe[j] > p1)      { p2 = p1; i2 = i1; p1 = pe[j]; i1 = e + j; }
                else if (pe[j] > p2) { p2 = pe[j]; i2 = e + j; }
            }
        }

        float denom = p1 + p2 + EPS;
        out[token * 2 + 0] = (float)i1;
        out[token * 2 + 1] = (float)i2;
        out[2 * BSZ + token * 2 + 0] = p1 / denom;
        out[2 * BSZ + token * 2 + 1] = p2 / denom;
    }
}

extern "C" void kernel_launch(void* const* d_in, const int* in_sizes, int n_in,
                              void* d_out, int out_size)
{
    const float* x = (const float*)d_in[0];
    const float* w = (const float*)d_in[1];
    float* out = (float*)d_out;

    prep_w_kernel<<<(E_DIM * D_DIM + 255) / 256, 256>>>(w);

    static int configured = 0;
    if (!configured) {
        cudaFuncSetAttribute(topk_router_mma,
                             cudaFuncAttributeMaxDynamicSharedMemorySize, SMEM_TOTAL);
        configured = 1;
    }
    topk_router_mma<<<BSZ / TM, THREADS, SMEM_TOTAL>>>(x, out);
}

// round 4
// speedup vs baseline: 1.7361x; 1.0412x over previous
#include <cuda_runtime.h>
#include <cuda_bf16.h>
#include <cstdint>

// TopKRouter: mma.sync bf16 triple-split (6 terms, err ~2^-24).
// B pre-packed into per-lane MMA fragment layout (gmem, L1-hot) -> no B smem path.
// TM=64, grid=256, 2 CTAs/SM, 16 warps/SM.
// out (f32): [0,32768) topk_idx ; [32768,65536) topk_probs ; [65536,..) probs.

#define D_DIM   2048
#define E_DIM   64
#define BSZ     16384
#define TM      64
#define KC      32
#define NCHUNK  (D_DIM / KC)
#define THREADS 256
#define EPS     1e-9f

#define A_STRIDE 80                    // bytes per token row (32 bf16 + pad)
#define A_SPLIT  (TM * A_STRIDE)       // 5120
#define ABUF     (3 * A_SPLIT)         // 15360
#define SMEM_TOTAL (2 * ABUF)          // 30720 (logits 64*72*4=18432 overlays)
#define LS_STRIDE 72

// B fragments: [c(64)][ks(2)][s(3)][wn(2)][ldg(2)] blocks of 32 lanes x uint4
__device__ uint4 g_bfrag[NCHUNK * 2 * 3 * 2 * 2 * 32];

__device__ __forceinline__ uint32_t pack2(__nv_bfloat16 a, __nv_bfloat16 b) {
    __nv_bfloat162 t; t.x = a; t.y = b;
    return *(uint32_t*)&t;
}
__device__ __forceinline__ __nv_bfloat16 split_sel(float v, int s) {
    __nv_bfloat16 bh = __float2bfloat16_rn(v);
    if (s == 0) return bh;
    float r1 = v - __bfloat162float(bh);
    __nv_bfloat16 bm = __float2bfloat16_rn(r1);
    if (s == 1) return bm;
    return __float2bfloat16_rn(r1 - __bfloat162float(bm));
}

// one thread per (c,ks,s,wn,ldg,lane) -> one uint4 (two n8 tiles' {b0,b1})
__global__ void prep_w_kernel(const float* __restrict__ w) {
    int t = blockIdx.x * blockDim.x + threadIdx.x;
    if (t >= NCHUNK * 2 * 3 * 2 * 2 * 32) return;
    int lane = t & 31;
    int rest = t >> 5;
    int ldg = rest & 1;  rest >>= 1;
    int wn  = rest & 1;  rest >>= 1;
    int s   = rest % 3;  rest /= 3;
    int ks  = rest & 1;  rest >>= 1;
    int c   = rest;
    uint32_t r[4];
    #pragma unroll
    for (int tt = 0; tt < 2; tt++) {
        int nn = wn * 32 + (ldg * 2 + tt) * 8 + (lane >> 2);
        #pragma unroll
        for (int bb = 0; bb < 2; bb++) {
            int k0 = c * KC + ks * 16 + bb * 8 + 2 * (lane & 3);
            float v0 = w[(size_t)nn * D_DIM + k0];
            float v1 = w[(size_t)nn * D_DIM + k0 + 1];
            r[tt * 2 + bb] = pack2(split_sel(v0, s), split_sel(v1, s));
        }
    }
    g_bfrag[t] = make_uint4(r[0], r[1], r[2], r[3]);
}

__device__ __forceinline__ uint32_t smem_u32(const void* p) {
    uint32_t a;
    asm("{ .reg .u64 t; cvta.to.shared.u64 t, %1; cvt.u32.u64 %0, t; }" : "=r"(a) : "l"(p));
    return a;
}
__device__ __forceinline__ void ldsm4(uint32_t* r, uint32_t addr) {
    asm volatile("ldmatrix.sync.aligned.m8n8.x4.shared.b16 {%0,%1,%2,%3}, [%4];"
        : "=r"(r[0]), "=r"(r[1]), "=r"(r[2]), "=r"(r[3]) : "r"(addr));
}
__device__ __forceinline__ void mma16816(float* d, const uint32_t* a,
                                         uint32_t b0, uint32_t b1) {
    asm volatile(
        "mma.sync.aligned.m16n8k16.row.col.f32.bf16.bf16.f32 "
        "{%0,%1,%2,%3}, {%4,%5,%6,%7}, {%8,%9}, {%0,%1,%2,%3};"
        : "+f"(d[0]), "+f"(d[1]), "+f"(d[2]), "+f"(d[3])
        : "r"(a[0]), "r"(a[1]), "r"(a[2]), "r"(a[3]), "r"(b0), "r"(b1));
}

__global__ __launch_bounds__(THREADS, 2)
void topk_router_mma(const float* __restrict__ x, float* __restrict__ out)
{
    extern __shared__ char smem[];
    const uint32_t sbase = smem_u32(smem);
    const int tid  = threadIdx.x;
    const int wid  = tid >> 5;
    const int lane = tid & 31;
    const int wm   = wid >> 1;     // 0..3 -> 16-row slice
    const int wn   = wid & 1;      // 0..1 -> 32-col slice
    const int m0   = blockIdx.x * TM;

    // A ldmatrix base (relative to smem start, per split)
    uint32_t a_off[3];
    #pragma unroll
    for (int s = 0; s < 3; s++)
        a_off[s] = s * A_SPLIT + (wm * 16 + (lane & 15)) * A_STRIDE
                 + (lane >> 4) * 16;

    // x staging: each thread 8 floats: row tid>>2, k-block (tid&3)*8
    const int xrow = tid >> 2;
    const int xkb  = (tid & 3) * 8;
    const size_t xbase = (size_t)(m0 + xrow) * D_DIM + xkb;
    float4 xv[2];

    #define LDG_CHUNK(c) do {                                                 \
        xv[0] = *(const float4*)&x[xbase + (c) * KC];                         \
        xv[1] = *(const float4*)&x[xbase + (c) * KC + 4];                     \
    } while (0)

    #define STS_CHUNK(bufoff) do {                                            \
        _Pragma("unroll")                                                     \
        for (int i = 0; i < 2; i++) {                                         \
            float vv[4] = {xv[i].x, xv[i].y, xv[i].z, xv[i].w};               \
            __nv_bfloat16 hh[4], mm[4], ll[4];                                \
            _Pragma("unroll")                                                 \
            for (int e = 0; e < 4; e++) {                                     \
                hh[e] = __float2bfloat16_rn(vv[e]);                           \
                float r1 = vv[e] - __bfloat162float(hh[e]);                   \
                mm[e] = __float2bfloat16_rn(r1);                              \
                float r2 = r1 - __bfloat162float(mm[e]);                      \
                ll[e] = __float2bfloat16_rn(r2);                              \
            }                                                                 \
            char* pa = smem + (bufoff) + xrow * A_STRIDE + (xkb + i * 4) * 2; \
            *(uint2*)(pa + 0 * A_SPLIT) =                                     \
                make_uint2(pack2(hh[0], hh[1]), pack2(hh[2], hh[3]));         \
            *(uint2*)(pa + 1 * A_SPLIT) =                                     \
                make_uint2(pack2(mm[0], mm[1]), pack2(mm[2], mm[3]));         \
            *(uint2*)(pa + 2 * A_SPLIT) =                                     \
                make_uint2(pack2(ll[0], ll[1]), pack2(ll[2], ll[3]));         \
        }                                                                     \
    } while (0)

    float acc[4][4];
    #pragma unroll
    for (int j = 0; j < 4; j++)
        #pragma unroll
        for (int q = 0; q < 4; q++) acc[j][q] = 0.0f;

    LDG_CHUNK(0);
    STS_CHUNK(0);
    __syncthreads();

    const int ta[6] = {0, 0, 1, 0, 2, 1};
    const int tb[6] = {0, 1, 0, 2, 0, 1};

    #pragma unroll 1
    for (int c = 0; c < NCHUNK; c++) {
        const uint32_t bo = (c & 1) ? ABUF : 0u;
        if (c + 1 < NCHUNK) LDG_CHUNK(c + 1);

        #pragma unroll
        for (int ks = 0; ks < 2; ks++) {
            // B fragments for this (c, ks): 3 splits x 2 LDG.128 (L1-hot)
            uint4 q[3][2];
            #pragma unroll
            for (int s = 0; s < 3; s++) {
                int fb = ((((c * 2 + ks) * 3 + s) * 2 + wn) * 2) * 32 + lane;
                q[s][0] = g_bfrag[fb];
                q[s][1] = g_bfrag[fb + 32];
            }
            // A fragments: 3 splits x ldsm.x4 (m16k16)
            uint32_t a[3][4];
            #pragma unroll
            for (int s = 0; s < 3; s++)
                ldsm4(a[s], sbase + bo + a_off[s] + ks * 32);

            #pragma unroll
            for (int t = 0; t < 6; t++) {
                const uint4* qq = q[tb[t]];
                mma16816(acc[0], a[ta[t]], qq[0].x, qq[0].y);
                mma16816(acc[1], a[ta[t]], qq[0].z, qq[0].w);
                mma16816(acc[2], a[ta[t]], qq[1].x, qq[1].y);
                mma16816(acc[3], a[ta[t]], qq[1].z, qq[1].w);
            }
        }

        if (c + 1 < NCHUNK) STS_CHUNK((c & 1) ? 0u : ABUF);
        __syncthreads();
    }

    // ---- stash logits to smem (overlay buffers) ----
    float* ls = (float*)smem;
    {
        int row = wm * 16 + (lane >> 2);
        int colb = wn * 32 + 2 * (lane & 3);
        #pragma unroll
        for (int j = 0; j < 4; j++) {
            *(float2*)&ls[row * LS_STRIDE + colb + j * 8] =
                make_float2(acc[j][0], acc[j][1]);
            *(float2*)&ls[(row + 8) * LS_STRIDE + colb + j * 8] =
                make_float2(acc[j][2], acc[j][3]);
        }
    }
    __syncthreads();

    // ---- softmax + top-2, one token per thread ----
    if (tid < TM) {
        const int token = m0 + tid;
        float* row = &ls[tid * LS_STRIDE];

        float mx = -1e30f;
        #pragma unroll
        for (int e = 0; e < E_DIM; e++) mx = fmaxf(mx, row[e]);

        float sum = 0.0f;
        #pragma unroll
        for (int e = 0; e < E_DIM; e++) {
            float ev = expf(row[e] - mx);
            row[e] = ev;
            sum += ev;
        }
        float inv = 1.0f / sum;

        float* __restrict__ out_p = out + 4 * BSZ + (size_t)token * E_DIM;
        float p1 = -1.0f, p2 = -1.0f;
        int   i1 = 0,     i2 = 0;
        #pragma unroll
        for (int e = 0; e < E_DIM; e += 4) {
            float4 pv = make_float4(row[e] * inv, row[e+1] * inv,
                                    row[e+2] * inv, row[e+3] * inv);
            *(float4*)&out_p[e] = pv;
            float pe[4] = {pv.x, pv.y, pv.z, pv.w};
            #pragma unroll
            for (int j = 0; j < 4; j++) {
                if (pe[j] > p1)      { p2 = p1; i2 = i1; p1 = pe[j]; i1 = e + j; }
                else if (pe[j] > p2) { p2 = pe[j]; i2 = e + j; }
            }
        }

        float denom = p1 + p2 + EPS;
        out[token * 2 + 0] = (float)i1;
        out[token * 2 + 1] = (float)i2;
        out[2 * BSZ + token * 2 + 0] = p1 / denom;
        out[2 * BSZ + token * 2 + 1] = p2 / denom;
    }
}

extern "C" void kernel_launch(void* const* d_in, const int* in_sizes, int n_in,
                              void* d_out, int out_size)
{
    const float* x = (const float*)d_in[0];
    const float* w = (const float*)d_in[1];
    float* out = (float*)d_out;

    prep_w_kernel<<<(NCHUNK * 2 * 3 * 2 * 2 * 32 + 255) / 256, 256>>>(w);

    static int configured = 0;
    if (!configured) {
        cudaFuncSetAttribute(topk_router_mma,
                             cudaFuncAttributeMaxDynamicSharedMemorySize, SMEM_TOTAL);
        configured = 1;
    }
    topk_router_mma<<<BSZ / TM, THREADS, SMEM_TOTAL>>>(x, out);
}

// round 5
// speedup vs baseline: 1.7916x; 1.0320x over previous
#include <cuda_runtime.h>
#include <cuda_bf16.h>
#include <cstdint>

// TopKRouter: mma.sync bf16 2-way split, 3 terms (hh+hm+mh), err ~1e-5.
// B pre-packed as per-lane MMA fragments in gmem (L1/L2-hot).
// TM=64 x n64 warps, 128 thr/CTA, grid 256, 4 CTAs/SM.
// out (f32): [0,32768) topk_idx ; [32768,65536) topk_probs ; [65536,..) probs.

#define D_DIM   2048
#define E_DIM   64
#define BSZ     16384
#define TM      64
#define KC      32
#define NCHUNK  (D_DIM / KC)
#define THREADS 128
#define EPS     1e-9f

#define A_STRIDE 80                    // bytes per token row (32 bf16 + 16B pad)
#define A_SPLIT  (TM * A_STRIDE)       // 5120
#define ABUF     (2 * A_SPLIT)         // 10240 (h,m splits)
#define SMEM_TOTAL (2 * ABUF)          // 20480 double-buffered
#define LS_STRIDE 68                   // floats per logits row

// B fragments: [c(64)][ks(2)][s(2)][g(4)][lane(32)] uint4
__device__ uint4 g_bfrag[NCHUNK * 2 * 2 * 4 * 32];

__device__ __forceinline__ uint32_t pack2(__nv_bfloat16 a, __nv_bfloat16 b) {
    __nv_bfloat162 t; t.x = a; t.y = b;
    return *(uint32_t*)&t;
}
__device__ __forceinline__ __nv_bfloat16 split_sel(float v, int s) {
    __nv_bfloat16 bh = __float2bfloat16_rn(v);
    if (s == 0) return bh;
    return __float2bfloat16_rn(v - __bfloat162float(bh));
}

__global__ void prep_w_kernel(const float* __restrict__ w) {
    int t = blockIdx.x * blockDim.x + threadIdx.x;
    if (t >= NCHUNK * 2 * 2 * 4 * 32) return;
    int lane = t & 31;
    int rest = t >> 5;
    int g  = rest & 3;  rest >>= 2;
    int s  = rest & 1;  rest >>= 1;
    int ks = rest & 1;  rest >>= 1;
    int c  = rest;
    uint32_t r[4];
    #pragma unroll
    for (int tt = 0; tt < 2; tt++) {
        int n = (g * 2 + tt) * 8 + (lane >> 2);
        #pragma unroll
        for (int bb = 0; bb < 2; bb++) {
            int k0 = c * KC + ks * 16 + bb * 8 + 2 * (lane & 3);
            float v0 = w[(size_t)n * D_DIM + k0];
            float v1 = w[(size_t)n * D_DIM + k0 + 1];
            r[tt * 2 + bb] = pack2(split_sel(v0, s), split_sel(v1, s));
        }
    }
    g_bfrag[t] = make_uint4(r[0], r[1], r[2], r[3]);
}

__device__ __forceinline__ uint32_t smem_u32(const void* p) {
    uint32_t a;
    asm("{ .reg .u64 t; cvta.to.shared.u64 t, %1; cvt.u32.u64 %0, t; }" : "=r"(a) : "l"(p));
    return a;
}
__device__ __forceinline__ void ldsm4(uint32_t* r, uint32_t addr) {
    asm volatile("ldmatrix.sync.aligned.m8n8.x4.shared.b16 {%0,%1,%2,%3}, [%4];"
        : "=r"(r[0]), "=r"(r[1]), "=r"(r[2]), "=r"(r[3]) : "r"(addr));
}
__device__ __forceinline__ void mma16816(float* d, const uint32_t* a,
                                         uint32_t b0, uint32_t b1) {
    asm volatile(
        "mma.sync.aligned.m16n8k16.row.col.f32.bf16.bf16.f32 "
        "{%0,%1,%2,%3}, {%4,%5,%6,%7}, {%8,%9}, {%0,%1,%2,%3};"
        : "+f"(d[0]), "+f"(d[1]), "+f"(d[2]), "+f"(d[3])
        : "r"(a[0]), "r"(a[1]), "r"(a[2]), "r"(a[3]), "r"(b0), "r"(b1));
}

__global__ __launch_bounds__(THREADS, 4)
void topk_router_mma(const float* __restrict__ x, float* __restrict__ out)
{
    extern __shared__ char smem[];
    const uint32_t sbase = smem_u32(smem);
    const int tid  = threadIdx.x;
    const int wid  = tid >> 5;     // 0..3: 16-row slice, all 64 cols
    const int lane = tid & 31;
    const int m0   = blockIdx.x * TM;

    uint32_t a_off[2];
    #pragma unroll
    for (int s = 0; s < 2; s++)
        a_off[s] = s * A_SPLIT + (wid * 16 + (lane & 15)) * A_STRIDE
                 + (lane >> 4) * 16;

    float4 xv[4];

    // linear float4 mapping: l = i*128 + tid ; row = l>>3 ; c4 = (l&7)*4
    #define LDG_CHUNK(c) do {                                                 \
        _Pragma("unroll")                                                     \
        for (int i = 0; i < 4; i++) {                                         \
            int l = i * THREADS + tid;                                        \
            xv[i] = *(const float4*)&x[(size_t)(m0 + (l >> 3)) * D_DIM        \
                                       + (c) * KC + (l & 7) * 4];             \
        }                                                                     \
    } while (0)

    #define STS_CHUNK(bufoff) do {                                            \
        _Pragma("unroll")                                                     \
        for (int i = 0; i < 4; i++) {                                         \
            int l = i * THREADS + tid;                                        \
            int row = l >> 3, c4 = (l & 7) * 4;                               \
            float vv[4] = {xv[i].x, xv[i].y, xv[i].z, xv[i].w};               \
            __nv_bfloat16 hh[4], mm[4];                                       \
            _Pragma("unroll")                                                 \
            for (int e = 0; e < 4; e++) {                                     \
                hh[e] = __float2bfloat16_rn(vv[e]);                           \
                mm[e] = __float2bfloat16_rn(vv[e] - __bfloat162float(hh[e])); \
            }                                                                 \
            char* pa = smem + (bufoff) + row * A_STRIDE + c4 * 2;             \
            *(uint2*)(pa + 0 * A_SPLIT) =                                     \
                make_uint2(pack2(hh[0], hh[1]), pack2(hh[2], hh[3]));         \
            *(uint2*)(pa + 1 * A_SPLIT) =                                     \
                make_uint2(pack2(mm[0], mm[1]), pack2(mm[2], mm[3]));         \
        }                                                                     \
    } while (0)

    float acc[8][4];
    #pragma unroll
    for (int j = 0; j < 8; j++)
        #pragma unroll
        for (int q = 0; q < 4; q++) acc[j][q] = 0.0f;

    LDG_CHUNK(0);
    STS_CHUNK(0);
    __syncthreads();

    #pragma unroll 1
    for (int c = 0; c < NCHUNK; c++) {
        const uint32_t bo = (c & 1) ? ABUF : 0u;
        if (c + 1 < NCHUNK) LDG_CHUNK(c + 1);

        #pragma unroll
        for (int ks = 0; ks < 2; ks++) {
            uint32_t a[2][4];
            ldsm4(a[0], sbase + bo + a_off[0] + ks * 32);
            ldsm4(a[1], sbase + bo + a_off[1] + ks * 32);

            const int fb = ((c * 2 + ks) * 2) * 4 * 32 + lane;
            uint4 qh[4], qm[4];
            #pragma unroll
            for (int g = 0; g < 4; g++) {
                qh[g] = g_bfrag[fb + g * 32];
                qm[g] = g_bfrag[fb + 128 + g * 32];
            }

            #pragma unroll
            for (int g = 0; g < 4; g++) {
                mma16816(acc[2*g],   a[0], qh[g].x, qh[g].y);   // hh
                mma16816(acc[2*g+1], a[0], qh[g].z, qh[g].w);
                mma16816(acc[2*g],   a[0], qm[g].x, qm[g].y);   // hm
                mma16816(acc[2*g+1], a[0], qm[g].z, qm[g].w);
                mma16816(acc[2*g],   a[1], qh[g].x, qh[g].y);   // mh
                mma16816(acc[2*g+1], a[1], qh[g].z, qh[g].w);
            }
        }

        if (c + 1 < NCHUNK) STS_CHUNK((c & 1) ? 0u : ABUF);
        __syncthreads();
    }

    // ---- stash logits to smem (overlay buffers) ----
    float* ls = (float*)smem;
    {
        int row  = wid * 16 + (lane >> 2);
        int colb = 2 * (lane & 3);
        #pragma unroll
        for (int j = 0; j < 8; j++) {
            *(float2*)&ls[row * LS_STRIDE + colb + j * 8] =
                make_float2(acc[j][0], acc[j][1]);
            *(float2*)&ls[(row + 8) * LS_STRIDE + colb + j * 8] =
                make_float2(acc[j][2], acc[j][3]);
        }
    }
    __syncthreads();

    // ---- softmax + top-2, one token per thread ----
    if (tid < TM) {
        const int token = m0 + tid;
        float* row = &ls[tid * LS_STRIDE];

        float mx = -1e30f;
        #pragma unroll
        for (int e = 0; e < E_DIM; e++) mx = fmaxf(mx, row[e]);

        float sum = 0.0f;
        #pragma unroll
        for (int e = 0; e < E_DIM; e++) {
            float ev = expf(row[e] - mx);
            row[e] = ev;
            sum += ev;
        }
        float inv = 1.0f / sum;

        float* __restrict__ out_p = out + 4 * BSZ + (size_t)token * E_DIM;
        float p1 = -1.0f, p2 = -1.0f;
        int   i1 = 0,     i2 = 0;
        #pragma unroll
        for (int e = 0; e < E_DIM; e += 4) {
            float4 pv = make_float4(row[e] * inv, row[e+1] * inv,
                                    row[e+2] * inv, row[e+3] * inv);
            *(float4*)&out_p[e] = pv;
            float pe[4] = {pv.x, pv.y, pv.z, pv.w};
            #pragma unroll
            for (int j = 0; j < 4; j++) {
                if (pe[j] > p1)      { p2 = p1; i2 = i1; p1 = pe[j]; i1 = e + j; }
                else if (pe[j] > p2) { p2 = pe[j]; i2 = e + j; }
            }
        }

        float denom = p1 + p2 + EPS;
        out[token * 2 + 0] = (float)i1;
        out[token * 2 + 1] = (float)i2;
        out[2 * BSZ + token * 2 + 0] = p1 / denom;
        out[2 * BSZ + token * 2 + 1] = p2 / denom;
    }
}

extern "C" void kernel_launch(void* const* d_in, const int* in_sizes, int n_in,
                              void* d_out, int out_size)
{
    const float* x = (const float*)d_in[0];
    const float* w = (const float*)d_in[1];
    float* out = (float*)d_out;

    prep_w_kernel<<<(NCHUNK * 2 * 2 * 4 * 32 + 255) / 256, 256>>>(w);

    static int configured = 0;
    if (!configured) {
        cudaFuncSetAttribute(topk_router_mma,
                             cudaFuncAttributeMaxDynamicSharedMemorySize, SMEM_TOTAL);
        configured = 1;
    }
    topk_router_mma<<<BSZ / TM, THREADS, SMEM_TOTAL>>>(x, out);
}

// round 6
// speedup vs baseline: 3.0172x; 1.6841x over previous
#include <cuda_runtime.h>
#include <cuda_bf16.h>
#include <cstdint>

// TopKRouter: mma.sync bf16 2-way split (hh+hm+mh), A-frags loaded DIRECTLY
// from gmem (no smem, no mainloop syncthreads), split-K warps.
// TM=32 tokens/CTA, 4 warps = 2 m-stripes x 2 K-halves, grid 512.
// out (f32): [0,32768) topk_idx ; [32768,65536) topk_probs ; [65536,..) probs.

#define D_DIM   2048
#define E_DIM   64
#define BSZ     16384
#define TM      32
#define KC      32
#define NCHUNK  (D_DIM / KC)
#define THREADS 128
#define EPS     1e-9f
#define LS_STRIDE 65

// B fragments: [c(64)][ks(2)][s(2)][g(4)][lane(32)] uint4
__device__ uint4 g_bfrag[NCHUNK * 2 * 2 * 4 * 32];

__device__ __forceinline__ uint32_t pack2(__nv_bfloat16 a, __nv_bfloat16 b) {
    __nv_bfloat162 t; t.x = a; t.y = b;
    return *(uint32_t*)&t;
}
__device__ __forceinline__ __nv_bfloat16 split_sel(float v, int s) {
    __nv_bfloat16 bh = __float2bfloat16_rn(v);
    if (s == 0) return bh;
    return __float2bfloat16_rn(v - __bfloat162float(bh));
}

__global__ void prep_w_kernel(const float* __restrict__ w) {
    int t = blockIdx.x * blockDim.x + threadIdx.x;
    if (t >= NCHUNK * 2 * 2 * 4 * 32) return;
    int lane = t & 31;
    int rest = t >> 5;
    int g  = rest & 3;  rest >>= 2;
    int s  = rest & 1;  rest >>= 1;
    int ks = rest & 1;  rest >>= 1;
    int c  = rest;
    uint32_t r[4];
    #pragma unroll
    for (int tt = 0; tt < 2; tt++) {
        int n = (g * 2 + tt) * 8 + (lane >> 2);
        #pragma unroll
        for (int bb = 0; bb < 2; bb++) {
            int k0 = c * KC + ks * 16 + bb * 8 + 2 * (lane & 3);
            float v0 = w[(size_t)n * D_DIM + k0];
            float v1 = w[(size_t)n * D_DIM + k0 + 1];
            r[tt * 2 + bb] = pack2(split_sel(v0, s), split_sel(v1, s));
        }
    }
    g_bfrag[t] = make_uint4(r[0], r[1], r[2], r[3]);
}

__device__ __forceinline__ void mma16816(float* d, const uint32_t* a,
                                         uint32_t b0, uint32_t b1) {
    asm volatile(
        "mma.sync.aligned.m16n8k16.row.col.f32.bf16.bf16.f32 "
        "{%0,%1,%2,%3}, {%4,%5,%6,%7}, {%8,%9}, {%0,%1,%2,%3};"
        : "+f"(d[0]), "+f"(d[1]), "+f"(d[2]), "+f"(d[3])
        : "r"(a[0]), "r"(a[1]), "r"(a[2]), "r"(a[3]), "r"(b0), "r"(b1));
}

// pack float2 -> bf16x2 (hi = v.y, lo = v.x) and residual bf16x2
__device__ __forceinline__ void cvt_split(float2 v, uint32_t& h, uint32_t& m) {
    asm("cvt.rn.bf16x2.f32 %0, %1, %2;" : "=r"(h) : "f"(v.y), "f"(v.x));
    float h0 = __uint_as_float(h << 16);
    float h1 = __uint_as_float(h & 0xffff0000u);
    float r0 = v.x - h0;
    float r1 = v.y - h1;
    asm("cvt.rn.bf16x2.f32 %0, %1, %2;" : "=r"(m) : "f"(r1), "f"(r0));
}

__global__ __launch_bounds__(THREADS, 4)
void topk_router_mma(const float* __restrict__ x, float* __restrict__ out)
{
    __shared__ float ls[TM][LS_STRIDE];

    const int tid  = threadIdx.x;
    const int wid  = tid >> 5;
    const int lane = tid & 31;
    const int ms   = wid & 1;      // m-stripe (16 rows)
    const int kg   = wid >> 1;     // K half
    const int m0w  = blockIdx.x * TM + ms * 16;
    const int g    = lane >> 2;
    const int t4   = lane & 3;

    const float* xr0 = x + (size_t)(m0w + g)     * D_DIM + t4 * 2;
    const float* xr1 = x + (size_t)(m0w + g + 8) * D_DIM + t4 * 2;

    float acc[8][4];
    #pragma unroll
    for (int j = 0; j < 8; j++)
        #pragma unroll
        for (int q = 0; q < 4; q++) acc[j][q] = 0.0f;

    const int c0 = kg * (NCHUNK / 2);

    #pragma unroll 1
    for (int c = c0; c < c0 + NCHUNK / 2; c++) {
        #pragma unroll
        for (int ks = 0; ks < 2; ks++) {
            // B fragments (L1/L2-hot): 8 x LDG.128
            const int fb = ((c * 2 + ks) * 2) * 4 * 32 + lane;
            uint4 qh[4], qm[4];
            #pragma unroll
            for (int gg = 0; gg < 4; gg++) {
                qh[gg] = g_bfrag[fb + gg * 32];
                qm[gg] = g_bfrag[fb + 128 + gg * 32];
            }

            // A fragments: 4 x LDG.64 straight from x
            const int kb = c * KC + ks * 16;
            float2 v0 = *(const float2*)&xr0[kb];
            float2 v1 = *(const float2*)&xr1[kb];
            float2 v2 = *(const float2*)&xr0[kb + 8];
            float2 v3 = *(const float2*)&xr1[kb + 8];

            uint32_t ah[4], am[4];
            cvt_split(v0, ah[0], am[0]);
            cvt_split(v1, ah[1], am[1]);
            cvt_split(v2, ah[2], am[2]);
            cvt_split(v3, ah[3], am[3]);

            #pragma unroll
            for (int gg = 0; gg < 4; gg++) {
                mma16816(acc[2*gg],   ah, qh[gg].x, qh[gg].y);   // hh
                mma16816(acc[2*gg+1], ah, qh[gg].z, qh[gg].w);
                mma16816(acc[2*gg],   ah, qm[gg].x, qm[gg].y);   // hm
                mma16816(acc[2*gg+1], ah, qm[gg].z, qm[gg].w);
                mma16816(acc[2*gg],   am, qh[gg].x, qh[gg].y);   // mh
                mma16816(acc[2*gg+1], am, qh[gg].z, qh[gg].w);
            }
        }
    }

    // ---- combine K halves + stash logits ----
    const int row  = ms * 16 + (lane >> 2);
    const int colb = 2 * (lane & 3);

    if (kg == 1) {
        #pragma unroll
        for (int j = 0; j < 8; j++) {
            ls[row][colb + j * 8]     = acc[j][0];
            ls[row][colb + j * 8 + 1] = acc[j][1];
            ls[row + 8][colb + j * 8]     = acc[j][2];
            ls[row + 8][colb + j * 8 + 1] = acc[j][3];
        }
    }
    __syncthreads();
    if (kg == 0) {
        #pragma unroll
        for (int j = 0; j < 8; j++) {
            ls[row][colb + j * 8]     += acc[j][0];
            ls[row][colb + j * 8 + 1] += acc[j][1];
            ls[row + 8][colb + j * 8]     += acc[j][2];
            ls[row + 8][colb + j * 8 + 1] += acc[j][3];
        }
    }
    __syncthreads();

    // ---- softmax + top-2, one token per thread ----
    if (tid < TM) {
        const int token = blockIdx.x * TM + tid;
        float* row_p = &ls[tid][0];

        float mx = -1e30f;
        #pragma unroll
        for (int e = 0; e < E_DIM; e++) mx = fmaxf(mx, row_p[e]);

        float sum = 0.0f;
        #pragma unroll
        for (int e = 0; e < E_DIM; e++) {
            float ev = expf(row_p[e] - mx);
            row_p[e] = ev;
            sum += ev;
        }
        float inv = 1.0f / sum;

        float* __restrict__ out_p = out + 4 * BSZ + (size_t)token * E_DIM;
        float p1 = -1.0f, p2 = -1.0f;
        int   i1 = 0,     i2 = 0;
        #pragma unroll
        for (int e = 0; e < E_DIM; e += 4) {
            float4 pv = make_float4(row_p[e] * inv, row_p[e+1] * inv,
                                    row_p[e+2] * inv, row_p[e+3] * inv);
            *(float4*)&out_p[e] = pv;
            float pe[4] = {pv.x, pv.y, pv.z, pv.w};
            #pragma unroll
            for (int j = 0; j < 4; j++) {
                if (pe[j] > p1)      { p2 = p1; i2 = i1; p1 = pe[j]; i1 = e + j; }
                else if (pe[j] > p2) { p2 = pe[j]; i2 = e + j; }
            }
        }

        float denom = p1 + p2 + EPS;
        out[token * 2 + 0] = (float)i1;
        out[token * 2 + 1] = (float)i2;
        out[2 * BSZ + token * 2 + 0] = p1 / denom;
        out[2 * BSZ + token * 2 + 1] = p2 / denom;
    }
}

extern "C" void kernel_launch(void* const* d_in, const int* in_sizes, int n_in,
                              void* d_out, int out_size)
{
    const float* x = (const float*)d_in[0];
    const float* w = (const float*)d_in[1];
    float* out = (float*)d_out;

    prep_w_kernel<<<(NCHUNK * 2 * 2 * 4 * 32 + 255) / 256, 256>>>(w);
    topk_router_mma<<<BSZ / TM, THREADS>>>(x, out);
}